// round 14
// baseline (speedup 1.0000x reference)
#include <cuda_runtime.h>
#include <cuda_fp16.h>
#include <math.h>
#include <stdint.h>

// ---------------------------------------------------------------------------
// ProjectionDecoder fused kernel, 2 samples per CTA.
// Bilinear taps are channel-independent -> deconv channel-mix commutes with
// the resample. Pipeline:
//   rotate -> sig(196x10) -> wsig(196x16 fp16, pitch 24) -> comb (fp16,
//   packed HFMA2 tap mix, split kwlo/kwhi) -> output = bias + 4 comb halves.
// ---------------------------------------------------------------------------

#define NDEG 6
#define MTOT 49
#define JGRID 14

__constant__ float c_FACT[13] = {
    1.f, 1.f, 2.f, 6.f, 24.f, 120.f, 720.f, 5040.f, 40320.f,
    362880.f, 3628800.f, 39916800.f, 479001600.f};
__constant__ int c_OFF[8] = {0, 1, 10, 35, 84, 165, 286, 455};

__device__ float2 g_Yri[MTOT * 196];  // interleaved (Yre, Yim)
__device__ int4   g_toff[4096];   // 4 tap offsets, premultiplied by 24 (halves)
__device__ float4 g_tw[4096];     // 4 tap weights

// ---------------------------------------------------------------------------
__global__ void prep_kernel() {
    const int gid = blockIdx.x * blockDim.x + threadIdx.x;
    const float PI_F = 3.14159265358979323846f;

    if (gid < MTOT * 196) {
        const int midx = gid / 196;
        const int col = gid - midx * 196;
        const int jb = col / JGRID;
        const int k = col - jb * JGRID;
        int l = 0;
        while ((l + 1) * (l + 1) <= midx) ++l;
        const int ms = midx - (l * l + l);
        const int ma = ms < 0 ? -ms : ms;

        const float beta = PI_F * (2.0f * jb + 1.0f) / 28.0f;
        float x, sx;
        sincosf(beta, &sx, &x);

        float pmm = 1.0f;
        for (int m = 1; m <= ma; ++m) pmm = -(2.0f * m - 1.0f) * sx * pmm;
        float p = pmm;
        if (l > ma) {
            float pm1 = pmm;
            float pcur = (2.0f * ma + 1.0f) * x * pmm;
            for (int ll = ma + 2; ll <= l; ++ll) {
                float pn = ((2.0f * ll - 1.0f) * x * pcur -
                            (ll + ma - 1.0f) * pm1) / (float)(ll - ma);
                pm1 = pcur; pcur = pn;
            }
            p = pcur;
        }
        const float Nrm = sqrtf((2.0f * l + 1.0f) / (4.0f * PI_F) *
                                c_FACT[l - ma] / c_FACT[l + ma]);
        const float pr = Nrm * p;
        const float alpha = 2.0f * PI_F * (float)k / 14.0f;
        float sa, ca;
        sincosf((float)ma * alpha, &sa, &ca);
        float yre = pr * ca;
        float yim = pr * sa;
        if (ms < 0) {
            const float sgn = (ma & 1) ? -1.0f : 1.0f;
            yre = sgn * yre;
            yim = -sgn * yim;
        }
        g_Yri[gid] = make_float2(yre, yim);
    } else if (gid < MTOT * 196 + 4096) {
        const int p = gid - MTOT * 196;
        const int py = p >> 6, px = p & 63;
        const float r = 0.8f;
        const float yv = -r + py * (2.0f * r / 63.0f);
        const float xv = -r + px * (2.0f * r / 63.0f);
        float rho = sqrtf(xv * xv + yv * yv);
        if (rho > 1.0f) rho = 1.0f;
        const float th = asinf(rho);
        const float ph = atan2f(yv, xv);
        const float gx = ph / PI_F;
        const float gy = 2.0f * th / PI_F - 1.0f;
        const float gxp = (gx + 1.0f) * 7.0f - 0.5f;
        const float gyp = (gy + 1.0f) * 7.0f - 0.5f;
        const float x0f = floorf(gxp), y0f = floorf(gyp);
        const float wx1 = gxp - x0f, wx0 = 1.0f - wx1;
        const float wy1 = gyp - y0f, wy0 = 1.0f - wy1;
        const int xi0 = (int)x0f, yi0 = (int)y0f;
        const int xs[4] = {xi0, xi0 + 1, xi0, xi0 + 1};
        const int ys[4] = {yi0, yi0, yi0 + 1, yi0 + 1};
        const float ws[4] = {wx0 * wy0, wx1 * wy0, wx0 * wy1, wx1 * wy1};
        int o[4]; float w[4];
#pragma unroll
        for (int t = 0; t < 4; ++t) {
            const bool valid = (xs[t] >= 0) && (xs[t] < 14) &&
                               (ys[t] >= 0) && (ys[t] < 14);
            int xc = xs[t] < 0 ? 0 : (xs[t] > 13 ? 13 : xs[t]);
            int yc = ys[t] < 0 ? 0 : (ys[t] > 13 ? 13 : ys[t]);
            o[t] = (yc * 14 + xc) * 24;          // premultiplied: half pitch 24
            w[t] = valid ? ws[t] : 0.0f;
        }
        g_toff[p] = make_int4(o[0], o[1], o[2], o[3]);
        g_tw[p] = make_float4(w[0], w[1], w[2], w[3]);
    }
}

// ---------------------------------------------------------------------------
// smem layout (float index):
//  [0..159]        wt (10*16)
//  [160..4863]     wsig as half: 2 samples x 196 rows x pitch 24 halves
//  [4864.. )       SCRATCH:
//    front: per-sample (s=0,1) base 4864+s*1492:
//       +0 trig(56) +56 d(455) +512 Sre(490) +1002 Sim(490)
//    front: spectrum staging at 4864+2984 .. +3963 (980 floats)
//    later: comb halves: kwlo[4 kh][34 rows][136] then kwhi same
// ---------------------------------------------------------------------------
#define SM_WT     0
#define SM_WSIGH_F 160           // float offset of half wsig
#define WSIGH_PER_S 4704         // halves per sample (196*24)
#define SM_SCR    4864
#define PER_S     1492
#define OFF_TRIG  0
#define OFF_D     56
#define OFF_SRE   512
#define OFF_SIM   1002
#define OFF_SPEC  2984           // spectrum staging (within scratch)
#define CB_ROW    136            // halves per comb row (66 cols * 2, padded)
#define CB_PLANE  (34 * CB_ROW)  // 4624 halves per kh plane
#define CB_HI     (4 * CB_PLANE) // kwhi buffer offset (halves)
#define COMB_FLOATS (8 * CB_PLANE / 2)       // 18496 floats
#define SMEM_FLOATS (SM_SCR + COMB_FLOATS)   // 23360
#define SMEM_BYTES  (SMEM_FLOATS * 4)        // 93440

__device__ __forceinline__ float hx(unsigned v, int hi) {
    __half2 h2 = *reinterpret_cast<__half2*>(&v);
    return hi ? __high2float(h2) : __low2float(h2);
}
__device__ __forceinline__ unsigned hadd2u(unsigned a, unsigned b) {
    __half2 ha = *reinterpret_cast<__half2*>(&a);
    __half2 hb = *reinterpret_cast<__half2*>(&b);
    __half2 hc = __hadd2(ha, hb);
    return *reinterpret_cast<unsigned*>(&hc);
}
__device__ __forceinline__ unsigned hmul2u(__half2 w, unsigned v) {
    __half2 hv = *reinterpret_cast<__half2*>(&v);
    __half2 hc = __hmul2(w, hv);
    return *reinterpret_cast<unsigned*>(&hc);
}
__device__ __forceinline__ unsigned hfma2u(__half2 w, unsigned v, unsigned c) {
    __half2 hv = *reinterpret_cast<__half2*>(&v);
    __half2 hcv = *reinterpret_cast<__half2*>(&c);
    __half2 hr = __hfma2(w, hv, hcv);
    return *reinterpret_cast<unsigned*>(&hr);
}

// One phase-4 pixel: bilinear tap mix (HFMA2) into comb planes.
__device__ __forceinline__ void phase4_pixel(
    int p, int strip, const __half* __restrict__ wsb,
    __half* __restrict__ s_comb) {
    const int rr = p >> 6, x = p & 63;
    const int t = strip ? rr : rr + 1;
    const int iy = strip ? (31 + rr) : rr;
    const int pr = iy * 64 + x;
    const int4 o4 = g_toff[pr];
    const float4 w4 = g_tw[pr];
    const __half2 w0 = __float2half2_rn(w4.x);
    const __half2 w1 = __float2half2_rn(w4.y);
    const __half2 w2 = __float2half2_rn(w4.z);
    const __half2 w3 = __float2half2_rn(w4.w);

    const __half* v0 = wsb + o4.x;
    const __half* v1 = wsb + o4.y;
    const __half* v2 = wsb + o4.z;
    const __half* v3 = wsb + o4.w;
    uint4 a0 = *(const uint4*)(v0);
    uint4 a1 = *(const uint4*)(v0 + 8);
    uint4 b0 = *(const uint4*)(v1);
    uint4 b1 = *(const uint4*)(v1 + 8);
    uint4 c0 = *(const uint4*)(v2);
    uint4 c1 = *(const uint4*)(v2 + 8);
    uint4 d0 = *(const uint4*)(v3);
    uint4 d1 = *(const uint4*)(v3 + 8);

    unsigned acc[8];
    acc[0] = hadd2u(hfma2u(w1, b0.x, hmul2u(w0, a0.x)),
                    hfma2u(w3, d0.x, hmul2u(w2, c0.x)));
    acc[1] = hadd2u(hfma2u(w1, b0.y, hmul2u(w0, a0.y)),
                    hfma2u(w3, d0.y, hmul2u(w2, c0.y)));
    acc[2] = hadd2u(hfma2u(w1, b0.z, hmul2u(w0, a0.z)),
                    hfma2u(w3, d0.z, hmul2u(w2, c0.z)));
    acc[3] = hadd2u(hfma2u(w1, b0.w, hmul2u(w0, a0.w)),
                    hfma2u(w3, d0.w, hmul2u(w2, c0.w)));
    acc[4] = hadd2u(hfma2u(w1, b1.x, hmul2u(w0, a1.x)),
                    hfma2u(w3, d1.x, hmul2u(w2, c1.x)));
    acc[5] = hadd2u(hfma2u(w1, b1.y, hmul2u(w0, a1.y)),
                    hfma2u(w3, d1.y, hmul2u(w2, c1.y)));
    acc[6] = hadd2u(hfma2u(w1, b1.z, hmul2u(w0, a1.z)),
                    hfma2u(w3, d1.z, hmul2u(w2, c1.z)));
    acc[7] = hadd2u(hfma2u(w1, b1.w, hmul2u(w0, a1.w)),
                    hfma2u(w3, d1.w, hmul2u(w2, c1.w)));

    const int baseh = t * CB_ROW + (x + 1) * 2;
#pragma unroll
    for (int kh = 0; kh < 4; ++kh) {
        *(unsigned*)(s_comb + kh * CB_PLANE + baseh) = acc[2 * kh];
        *(unsigned*)(s_comb + CB_HI + kh * CB_PLANE + baseh) = acc[2 * kh + 1];
    }
}

__global__ __launch_bounds__(512, 2)
void decoder_kernel(const float* __restrict__ angles,
                    const float* __restrict__ spectrum,
                    const float* __restrict__ wt,
                    const float* __restrict__ bt,
                    float* __restrict__ out) {
    extern __shared__ float sm[];
    const int tid = threadIdx.x;
    const int n = blockIdx.x;   // handles samples 2n and 2n+1

    float* s_wt = sm + SM_WT;
    __half* s_wsigh = (__half*)(sm + SM_WSIGH_F);
    __half* s_comb = (__half*)(sm + SM_SCR);

    // ---- phase 0: trig tables (both samples) + staging ----
    if (tid < 64) {
        const int s = tid >> 5, t = tid & 31;
        float* st = sm + SM_SCR + s * PER_S + OFF_TRIG;
        const int ns = 2 * n + s;
        if (t < 13) {
            float al = angles[3 * ns + 0];
            float ga = angles[3 * ns + 2];
            float kk = (float)(t - 6);
            float si, co;
            sincosf(kk * al, &si, &co); st[13 + t] = si; st[0 + t] = co;
            sincosf(kk * ga, &si, &co); st[39 + t] = si; st[26 + t] = co;
        }
        if (t == 16) {
            float be = angles[3 * ns + 1];
            float si, co;
            sincosf(0.5f * be, &si, &co);
            st[52] = co; st[53] = si;
        }
    }
    for (int i = tid; i < 160; i += 512) s_wt[i] = wt[i];
    for (int i = tid; i < 980; i += 512) sm[SM_SCR + OFF_SPEC + i] = spectrum[i];
    __syncthreads();

    // ---- phase 1: Wigner small-d entries (455 per sample, 910 total) ----
    for (int u = tid; u < 910; u += 512) {
        const int s = (u >= 455);
        const int e = u - 455 * s;
        float* base = sm + SM_SCR + s * PER_S;
        const float cb = base[OFF_TRIG + 52], sb = base[OFF_TRIG + 53];
        int l = 0;
        while (l < 6 && e >= c_OFF[l + 1]) ++l;
        int r = e - c_OFF[l];
        int n1 = 2 * l + 1;
        int i = r / n1, j = r - i * n1;
        int mp = i - l, m = j - l;
        float pref = sqrtf(c_FACT[l + mp] * c_FACT[l - mp] *
                           c_FACT[l + m] * c_FACT[l - m]);
        int kmin = m - mp > 0 ? m - mp : 0;
        int kmax = (l + m) < (l - mp) ? (l + m) : (l - mp);
        float acc = 0.f;
        for (int k = kmin; k <= kmax; ++k) {
            float cc = pref / (c_FACT[l + m - k] * c_FACT[k] *
                               c_FACT[l - mp - k] * c_FACT[mp - m + k]);
            if ((mp - m + k) & 1) cc = -cc;
            int pc = 2 * l + m - mp - 2 * k;
            int ps = mp - m + 2 * k;
            float pcv = 1.f;
            for (int q = 0; q < pc; ++q) pcv *= cb;
            float psv = 1.f;
            for (int q = 0; q < ps; ++q) psv *= sb;
            acc += cc * pcv * psv;
        }
        base[OFF_D + e] = acc;
    }
    __syncthreads();

    // ---- phase 2: rotate spectrum -> Sre/Sim (49 x 10, pitch 10) ----
    {
        const float2* sp2 = (const float2*)(sm + SM_SCR + OFF_SPEC);
        for (int u = tid; u < 980; u += 512) {
            const int s = (u >= 490);
            const int idx = u - 490 * s;
            const int mrow = idx / 10, c = idx - mrow * 10;
            float* base = sm + SM_SCR + s * PER_S;
            int l = 0;
            while ((l + 1) * (l + 1) <= mrow) ++l;
            const int i = mrow - l * l;
            const int mp = i - l;
            const float camp = base[OFF_TRIG + 0 + mp + 6];
            const float samp = base[OFF_TRIG + 13 + mp + 6];
            const float* dptr = base + OFF_D + c_OFF[l] + i * (2 * l + 1);
            float are = 0.f, aim = 0.f;
            for (int j = 0; j <= 2 * l; ++j) {
                const int m = j - l;
                const float dv = dptr[j];
                const float cg = base[OFF_TRIG + 26 + m + 6];
                const float sg = base[OFF_TRIG + 39 + m + 6];
                const float cosang = camp * cg - samp * sg;
                const float sinang = samp * cg + camp * sg;
                const float2 sv = sp2[(l * l + j) * 10 + c];
                are += dv * (cosang * sv.x + sinang * sv.y);
                aim += dv * (cosang * sv.y - sinang * sv.x);
            }
            base[OFF_SRE + mrow * 10 + c] = are;
            base[OFF_SIM + mrow * 10 + c] = aim;
        }
    }
    __syncthreads();

    // ---- phase 3: sig[j][c] then wsig[j][k] = sum_c sig[j][c]*w[c][k] ----
    if (tid < 392) {
        const int s = (tid >= 196);
        const int j = tid - 196 * s;
        const float* sRe = sm + SM_SCR + s * PER_S + OFF_SRE;
        const float* sIm = sm + SM_SCR + s * PER_S + OFF_SIM;
        float acc[10];
#pragma unroll
        for (int c = 0; c < 10; ++c) acc[c] = 0.f;
#pragma unroll 7
        for (int m = 0; m < 49; ++m) {
            const float2 y = g_Yri[m * 196 + j];
            const float yre = y.x;
            const float yim = y.y;
            float2 r0 = *(const float2*)&sRe[m * 10 + 0];
            float2 r1 = *(const float2*)&sRe[m * 10 + 2];
            float2 r2 = *(const float2*)&sRe[m * 10 + 4];
            float2 r3 = *(const float2*)&sRe[m * 10 + 6];
            float2 r4 = *(const float2*)&sRe[m * 10 + 8];
            float2 i0 = *(const float2*)&sIm[m * 10 + 0];
            float2 i1 = *(const float2*)&sIm[m * 10 + 2];
            float2 i2 = *(const float2*)&sIm[m * 10 + 4];
            float2 i3 = *(const float2*)&sIm[m * 10 + 6];
            float2 i4 = *(const float2*)&sIm[m * 10 + 8];
            acc[0] += r0.x * yre - i0.x * yim;
            acc[1] += r0.y * yre - i0.y * yim;
            acc[2] += r1.x * yre - i1.x * yim;
            acc[3] += r1.y * yre - i1.y * yim;
            acc[4] += r2.x * yre - i2.x * yim;
            acc[5] += r2.y * yre - i2.y * yim;
            acc[6] += r3.x * yre - i3.x * yim;
            acc[7] += r3.y * yre - i3.y * yim;
            acc[8] += r4.x * yre - i4.x * yim;
            acc[9] += r4.y * yre - i4.y * yim;
        }
        // fold deconv weights -> fp16 wsig (storage only; math fp32)
        __half* wso = s_wsigh + s * WSIGH_PER_S + j * 24;
#pragma unroll
        for (int k8 = 0; k8 < 2; ++k8) {
            float4 wv0 = make_float4(0.f, 0.f, 0.f, 0.f);
            float4 wv1 = make_float4(0.f, 0.f, 0.f, 0.f);
#pragma unroll
            for (int c = 0; c < 10; ++c) {
                const float a = acc[c];
                float4 w0 = *(const float4*)&s_wt[c * 16 + k8 * 8];
                float4 w1 = *(const float4*)&s_wt[c * 16 + k8 * 8 + 4];
                wv0.x += a * w0.x; wv0.y += a * w0.y;
                wv0.z += a * w0.z; wv0.w += a * w0.w;
                wv1.x += a * w1.x; wv1.y += a * w1.y;
                wv1.z += a * w1.z; wv1.w += a * w1.w;
            }
            __half2 h0 = __floats2half2_rn(wv0.x, wv0.y);
            __half2 h1 = __floats2half2_rn(wv0.z, wv0.w);
            __half2 h2 = __floats2half2_rn(wv1.x, wv1.y);
            __half2 h3 = __floats2half2_rn(wv1.z, wv1.w);
            uint4 v;
            v.x = *reinterpret_cast<unsigned*>(&h0);
            v.y = *reinterpret_cast<unsigned*>(&h1);
            v.z = *reinterpret_cast<unsigned*>(&h2);
            v.w = *reinterpret_cast<unsigned*>(&h3);
            *(uint4*)(wso + k8 * 8) = v;
        }
    }

    const float bias = bt[0];

    // ---- phases 4 & 5: per sample, per 64-output-row strip ----
    for (int s = 0; s < 2; ++s) {
        const __half* wsb = s_wsigh + s * WSIGH_PER_S;
        for (int strip = 0; strip < 2; ++strip) {
            __syncthreads();   // comb free (prev phase5 done / scratch dead)

            // border zeroing
            {
                const int tz = strip ? 33 : 0;   // untouched comb row
                for (int i = tid; i < 8 * 66; i += 512) {
                    const int buf = i / 66, c2 = i - buf * 66;
                    unsigned* dst = (unsigned*)(s_comb + buf * CB_PLANE) +
                                    (tz * CB_ROW >> 1) + c2;
                    *dst = 0u;
                }
                if (s == 0 && strip == 0) {
                    for (int i = tid; i < 8 * 34; i += 512) {
                        const int buf = i / 34, rr2 = i - buf * 34;
                        unsigned* rowp = (unsigned*)(s_comb + buf * CB_PLANE +
                                                     rr2 * CB_ROW);
                        rowp[0] = 0u;
                        rowp[65] = 0u;
                    }
                }
            }

            // phase 4: exact trip count 2112 = 4*512 + 64 -> 4 full pixel
            // calls (no bounds checks) + 64-thread tail.
            phase4_pixel(tid, strip, wsb, s_comb);
            phase4_pixel(tid + 512, strip, wsb, s_comb);
            phase4_pixel(tid + 1024, strip, wsb, s_comb);
            phase4_pixel(tid + 1536, strip, wsb, s_comb);
            if (tid < 64) phase4_pixel(tid + 2048, strip, wsb, s_comb);
            __syncthreads();

            // phase 5: output = bias + 4 comb halves (wide, conflict-free)
            {
                const int b = tid & 15;          // col block (8 cols)
                const int a = tid >> 4;          // 0..31
                const int blk = a >> 1;          // 4-row block 0..15
                const int halfq = a & 1;
                const int rowbase = 2 * blk;

                const int R1[4] = {1, 2, 2, 3};
                const int KH1[4] = {1, 0, 1, 0};
                const int R2[4] = {0, 1, 1, 2};
                const int KH2[4] = {3, 2, 3, 2};

                float* op = out + (size_t)(2 * n + s) * 16384 +
                            (size_t)(64 * strip) * 128 + 8 * b;

#pragma unroll
                for (int q = 0; q < 2; ++q) {
                    const int dy = 2 * halfq + q;
                    const __half* lo1 = s_comb + KH1[dy] * CB_PLANE +
                                        (rowbase + R1[dy]) * CB_ROW + 8 * b;
                    const __half* lo2 = s_comb + KH2[dy] * CB_PLANE +
                                        (rowbase + R2[dy]) * CB_ROW + 8 * b;
                    const __half* hi1 = lo1 + CB_HI;
                    const __half* hi2 = lo2 + CB_HI;

                    // 24-B window per stream: uint4 (halves 0..7) + uint2 (8..11)
                    uint4 LaA = *(const uint4*)(lo1);
                    uint2 LaB = *(const uint2*)(lo1 + 8);
                    uint4 LbA = *(const uint4*)(lo2);
                    uint2 LbB = *(const uint2*)(lo2 + 8);
                    uint4 HaA = *(const uint4*)(hi1);
                    uint2 HaB = *(const uint2*)(hi1 + 8);
                    uint4 HbA = *(const uint4*)(hi2);
                    uint2 HbB = *(const uint2*)(hi2 + 8);

                    unsigned LL[6], HH[6];
                    LL[1] = hadd2u(LaA.y, LbA.y);
                    LL[2] = hadd2u(LaA.z, LbA.z);
                    LL[3] = hadd2u(LaA.w, LbA.w);
                    LL[4] = hadd2u(LaB.x, LbB.x);
                    LL[5] = hadd2u(LaB.y, LbB.y);
                    HH[0] = hadd2u(HaA.x, HbA.x);
                    HH[1] = hadd2u(HaA.y, HbA.y);
                    HH[2] = hadd2u(HaA.z, HbA.z);
                    HH[3] = hadd2u(HaA.w, HbA.w);
                    HH[4] = hadd2u(HaB.x, HbB.x);

                    float o[8];
#pragma unroll
                    for (int e = 0; e < 8; ++e) {
                        const int il = e + 3;
                        const int ih = e + 1;
                        o[e] = bias + hx(LL[il >> 1], il & 1) +
                               hx(HH[ih >> 1], ih & 1);
                    }
                    float* orow = op + (size_t)(4 * blk + dy) * 128;
                    *(float4*)(orow + 0) = make_float4(o[0], o[1], o[2], o[3]);
                    *(float4*)(orow + 4) = make_float4(o[4], o[5], o[6], o[7]);
                }
            }
        }
    }
}

// ---------------------------------------------------------------------------
extern "C" void kernel_launch(void* const* d_in, const int* in_sizes, int n_in,
                              void* d_out, int out_size) {
    const float* angles   = (const float*)d_in[0];
    const float* spectrum = (const float*)d_in[1];
    const float* wt       = (const float*)d_in[2];
    const float* bt       = (const float*)d_in[3];
    float* out = (float*)d_out;
    (void)in_sizes; (void)n_in; (void)out_size;

    cudaFuncSetAttribute(decoder_kernel,
                         cudaFuncAttributeMaxDynamicSharedMemorySize,
                         SMEM_BYTES);

    prep_kernel<<<54, 256>>>();
    decoder_kernel<<<1024, 512, SMEM_BYTES>>>(angles, spectrum, wt, bt, out);
}

// round 17
// speedup vs baseline: 1.0228x; 1.0228x over previous
#include <cuda_runtime.h>
#include <cuda_fp16.h>
#include <math.h>
#include <stdint.h>

// ---------------------------------------------------------------------------
// ProjectionDecoder fused kernel, 2 samples per CTA.
// Bilinear taps are channel-independent -> deconv channel-mix commutes with
// the resample. Pipeline:
//   rotate -> sig(196x10) -> wsig(196x16 fp16, pitch 24) -> comb (fp16,
//   packed HFMA2 tap mix, split kwlo/kwhi) -> output = bias + 4 comb halves.
// ---------------------------------------------------------------------------

#define NDEG 6
#define MTOT 49
#define JGRID 14

__constant__ float c_FACT[13] = {
    1.f, 1.f, 2.f, 6.f, 24.f, 120.f, 720.f, 5040.f, 40320.f,
    362880.f, 3628800.f, 39916800.f, 479001600.f};
__constant__ int c_OFF[8] = {0, 1, 10, 35, 84, 165, 286, 455};
__constant__ signed char c_L[49] = {
    0, 1, 1, 1, 2, 2, 2, 2, 2, 3, 3, 3, 3, 3, 3, 3,
    4, 4, 4, 4, 4, 4, 4, 4, 4, 5, 5, 5, 5, 5, 5, 5,
    5, 5, 5, 5, 6, 6, 6, 6, 6, 6, 6, 6, 6, 6, 6, 6, 6};

__device__ float2 g_Yri[MTOT * 196];  // interleaved (Yre, Yim)
__device__ int4   g_toff[4096];   // 4 tap offsets, premultiplied by 24 (halves)
__device__ float4 g_tw[4096];     // 4 tap weights

// ---------------------------------------------------------------------------
__global__ void prep_kernel() {
    const int gid = blockIdx.x * blockDim.x + threadIdx.x;
    const float PI_F = 3.14159265358979323846f;

    if (gid < MTOT * 196) {
        const int midx = gid / 196;
        const int col = gid - midx * 196;
        const int jb = col / JGRID;
        const int k = col - jb * JGRID;
        int l = 0;
        while ((l + 1) * (l + 1) <= midx) ++l;
        const int ms = midx - (l * l + l);
        const int ma = ms < 0 ? -ms : ms;

        const float beta = PI_F * (2.0f * jb + 1.0f) / 28.0f;
        float x, sx;
        sincosf(beta, &sx, &x);

        float pmm = 1.0f;
        for (int m = 1; m <= ma; ++m) pmm = -(2.0f * m - 1.0f) * sx * pmm;
        float p = pmm;
        if (l > ma) {
            float pm1 = pmm;
            float pcur = (2.0f * ma + 1.0f) * x * pmm;
            for (int ll = ma + 2; ll <= l; ++ll) {
                float pn = ((2.0f * ll - 1.0f) * x * pcur -
                            (ll + ma - 1.0f) * pm1) / (float)(ll - ma);
                pm1 = pcur; pcur = pn;
            }
            p = pcur;
        }
        const float Nrm = sqrtf((2.0f * l + 1.0f) / (4.0f * PI_F) *
                                c_FACT[l - ma] / c_FACT[l + ma]);
        const float pr = Nrm * p;
        const float alpha = 2.0f * PI_F * (float)k / 14.0f;
        float sa, ca;
        sincosf((float)ma * alpha, &sa, &ca);
        float yre = pr * ca;
        float yim = pr * sa;
        if (ms < 0) {
            const float sgn = (ma & 1) ? -1.0f : 1.0f;
            yre = sgn * yre;
            yim = -sgn * yim;
        }
        g_Yri[gid] = make_float2(yre, yim);
    } else if (gid < MTOT * 196 + 4096) {
        const int p = gid - MTOT * 196;
        const int py = p >> 6, px = p & 63;
        const float r = 0.8f;
        const float yv = -r + py * (2.0f * r / 63.0f);
        const float xv = -r + px * (2.0f * r / 63.0f);
        float rho = sqrtf(xv * xv + yv * yv);
        if (rho > 1.0f) rho = 1.0f;
        const float th = asinf(rho);
        const float ph = atan2f(yv, xv);
        const float gx = ph / PI_F;
        const float gy = 2.0f * th / PI_F - 1.0f;
        const float gxp = (gx + 1.0f) * 7.0f - 0.5f;
        const float gyp = (gy + 1.0f) * 7.0f - 0.5f;
        const float x0f = floorf(gxp), y0f = floorf(gyp);
        const float wx1 = gxp - x0f, wx0 = 1.0f - wx1;
        const float wy1 = gyp - y0f, wy0 = 1.0f - wy1;
        const int xi0 = (int)x0f, yi0 = (int)y0f;
        const int xs[4] = {xi0, xi0 + 1, xi0, xi0 + 1};
        const int ys[4] = {yi0, yi0, yi0 + 1, yi0 + 1};
        const float ws[4] = {wx0 * wy0, wx1 * wy0, wx0 * wy1, wx1 * wy1};
        int o[4]; float w[4];
#pragma unroll
        for (int t = 0; t < 4; ++t) {
            const bool valid = (xs[t] >= 0) && (xs[t] < 14) &&
                               (ys[t] >= 0) && (ys[t] < 14);
            int xc = xs[t] < 0 ? 0 : (xs[t] > 13 ? 13 : xs[t]);
            int yc = ys[t] < 0 ? 0 : (ys[t] > 13 ? 13 : ys[t]);
            o[t] = (yc * 14 + xc) * 24;          // premultiplied: half pitch 24
            w[t] = valid ? ws[t] : 0.0f;
        }
        g_toff[p] = make_int4(o[0], o[1], o[2], o[3]);
        g_tw[p] = make_float4(w[0], w[1], w[2], w[3]);
    }
}

// ---------------------------------------------------------------------------
// smem layout (float index):
//  [0..159]        wt (10*16)
//  [160..4863]     wsig as half: 2 samples x 196 rows x pitch 24 halves
//  [4864.. )       SCRATCH:
//    front: per-sample (s=0,1) base 4864+s*1492:
//       +0 trig(56) +56 d(455) +512 Sre(490) +1002 Sim(490)
//    front: spectrum staging at 4864+2984 .. +3963 (980 floats)
//    later: comb halves: kwlo[4 kh][34 rows][136] then kwhi same
// ---------------------------------------------------------------------------
#define SM_WT     0
#define SM_WSIGH_F 160           // float offset of half wsig
#define WSIGH_PER_S 4704         // halves per sample (196*24)
#define SM_SCR    4864
#define PER_S     1492
#define OFF_TRIG  0
#define OFF_D     56
#define OFF_SRE   512
#define OFF_SIM   1002
#define OFF_SPEC  2984           // spectrum staging (within scratch)
#define CB_ROW    136            // halves per comb row (66 cols * 2, padded)
#define CB_PLANE  (34 * CB_ROW)  // 4624 halves per kh plane
#define CB_HI     (4 * CB_PLANE) // kwhi buffer offset (halves)
#define COMB_FLOATS (8 * CB_PLANE / 2)       // 18496 floats
#define SMEM_FLOATS (SM_SCR + COMB_FLOATS)   // 23360
#define SMEM_BYTES  (SMEM_FLOATS * 4)        // 93440

__device__ __forceinline__ float hx(unsigned v, int hi) {
    __half2 h2 = *reinterpret_cast<__half2*>(&v);
    return hi ? __high2float(h2) : __low2float(h2);
}
__device__ __forceinline__ unsigned hadd2u(unsigned a, unsigned b) {
    __half2 ha = *reinterpret_cast<__half2*>(&a);
    __half2 hb = *reinterpret_cast<__half2*>(&b);
    __half2 hc = __hadd2(ha, hb);
    return *reinterpret_cast<unsigned*>(&hc);
}
__device__ __forceinline__ unsigned hmul2u(__half2 w, unsigned v) {
    __half2 hv = *reinterpret_cast<__half2*>(&v);
    __half2 hc = __hmul2(w, hv);
    return *reinterpret_cast<unsigned*>(&hc);
}
__device__ __forceinline__ unsigned hfma2u(__half2 w, unsigned v, unsigned c) {
    __half2 hv = *reinterpret_cast<__half2*>(&v);
    __half2 hcv = *reinterpret_cast<__half2*>(&c);
    __half2 hr = __hfma2(w, hv, hcv);
    return *reinterpret_cast<unsigned*>(&hr);
}

__global__ __launch_bounds__(512, 2)
void decoder_kernel(const float* __restrict__ angles,
                    const float* __restrict__ spectrum,
                    const float* __restrict__ wt,
                    const float* __restrict__ bt,
                    float* __restrict__ out) {
    extern __shared__ float sm[];
    const int tid = threadIdx.x;
    const int n = blockIdx.x;   // handles samples 2n and 2n+1

    float* s_wt = sm + SM_WT;
    __half* s_wsigh = (__half*)(sm + SM_WSIGH_F);
    __half* s_comb = (__half*)(sm + SM_SCR);

    // ---- phase 0: trig tables (both samples) + staging ----
    if (tid < 64) {
        const int s = tid >> 5, t = tid & 31;
        float* st = sm + SM_SCR + s * PER_S + OFF_TRIG;
        const int ns = 2 * n + s;
        if (t < 13) {
            float al = angles[3 * ns + 0];
            float ga = angles[3 * ns + 2];
            float kk = (float)(t - 6);
            float si, co;
            sincosf(kk * al, &si, &co); st[13 + t] = si; st[0 + t] = co;
            sincosf(kk * ga, &si, &co); st[39 + t] = si; st[26 + t] = co;
        }
        if (t == 16) {
            float be = angles[3 * ns + 1];
            float si, co;
            sincosf(0.5f * be, &si, &co);
            st[52] = co; st[53] = si;
        }
    }
    for (int i = tid; i < 160; i += 512) s_wt[i] = wt[i];
    for (int i = tid; i < 980; i += 512) sm[SM_SCR + OFF_SPEC + i] = spectrum[i];
    __syncthreads();

    // ---- phase 1: Wigner small-d entries (455 per sample, 910 total) ----
    for (int u = tid; u < 910; u += 512) {
        const int s = (u >= 455);
        const int e = u - 455 * s;
        float* base = sm + SM_SCR + s * PER_S;
        const float cb = base[OFF_TRIG + 52], sb = base[OFF_TRIG + 53];
        int l = 0;
        while (l < 6 && e >= c_OFF[l + 1]) ++l;
        int r = e - c_OFF[l];
        int n1 = 2 * l + 1;
        int i = r / n1, j = r - i * n1;
        int mp = i - l, m = j - l;
        float pref = sqrtf(c_FACT[l + mp] * c_FACT[l - mp] *
                           c_FACT[l + m] * c_FACT[l - m]);
        int kmin = m - mp > 0 ? m - mp : 0;
        int kmax = (l + m) < (l - mp) ? (l + m) : (l - mp);
        float acc = 0.f;
        for (int k = kmin; k <= kmax; ++k) {
            float cc = pref / (c_FACT[l + m - k] * c_FACT[k] *
                               c_FACT[l - mp - k] * c_FACT[mp - m + k]);
            if ((mp - m + k) & 1) cc = -cc;
            int pc = 2 * l + m - mp - 2 * k;
            int ps = mp - m + 2 * k;
            float pcv = 1.f;
            for (int q = 0; q < pc; ++q) pcv *= cb;
            float psv = 1.f;
            for (int q = 0; q < ps; ++q) psv *= sb;
            acc += cc * pcv * psv;
        }
        base[OFF_D + e] = acc;
    }
    __syncthreads();

    // ---- phase 2: rotate spectrum -> Sre/Sim (49 x 10, pitch 10) ----
    {
        const float2* sp2 = (const float2*)(sm + SM_SCR + OFF_SPEC);
        for (int u = tid; u < 980; u += 512) {
            const int s = (u >= 490);
            const int idx = u - 490 * s;
            const int mrow = idx / 10, c = idx - mrow * 10;
            float* base = sm + SM_SCR + s * PER_S;
            const int l = (int)c_L[mrow];
            const int ll2 = l * l;
            const int i = mrow - ll2;
            const int mp = i - l;
            const float camp = base[OFF_TRIG + 0 + mp + 6];
            const float samp = base[OFF_TRIG + 13 + mp + 6];
            const float* dptr = base + OFF_D + c_OFF[l] + i * (2 * l + 1);
            float are = 0.f, aim = 0.f;
            for (int j = 0; j <= 2 * l; ++j) {
                const int m = j - l;
                const float dv = dptr[j];
                const float cg = base[OFF_TRIG + 26 + m + 6];
                const float sg = base[OFF_TRIG + 39 + m + 6];
                const float cosang = camp * cg - samp * sg;
                const float sinang = samp * cg + camp * sg;
                const float2 sv = sp2[(ll2 + j) * 10 + c];
                are += dv * (cosang * sv.x + sinang * sv.y);
                aim += dv * (cosang * sv.y - sinang * sv.x);
            }
            base[OFF_SRE + mrow * 10 + c] = are;
            base[OFF_SIM + mrow * 10 + c] = aim;
        }
    }
    __syncthreads();

    // ---- phase 3: sig[j][c] then wsig[j][k] = sum_c sig[j][c]*w[c][k] ----
    if (tid < 392) {
        const int s = (tid >= 196);
        const int j = tid - 196 * s;
        const float* sRe = sm + SM_SCR + s * PER_S + OFF_SRE;
        const float* sIm = sm + SM_SCR + s * PER_S + OFF_SIM;
        float acc[10];
#pragma unroll
        for (int c = 0; c < 10; ++c) acc[c] = 0.f;
#pragma unroll 7
        for (int m = 0; m < 49; ++m) {
            const float2 y = g_Yri[m * 196 + j];
            const float yre = y.x;
            const float yim = y.y;
            float2 r0 = *(const float2*)&sRe[m * 10 + 0];
            float2 r1 = *(const float2*)&sRe[m * 10 + 2];
            float2 r2 = *(const float2*)&sRe[m * 10 + 4];
            float2 r3 = *(const float2*)&sRe[m * 10 + 6];
            float2 r4 = *(const float2*)&sRe[m * 10 + 8];
            float2 i0 = *(const float2*)&sIm[m * 10 + 0];
            float2 i1 = *(const float2*)&sIm[m * 10 + 2];
            float2 i2 = *(const float2*)&sIm[m * 10 + 4];
            float2 i3 = *(const float2*)&sIm[m * 10 + 6];
            float2 i4 = *(const float2*)&sIm[m * 10 + 8];
            acc[0] += r0.x * yre - i0.x * yim;
            acc[1] += r0.y * yre - i0.y * yim;
            acc[2] += r1.x * yre - i1.x * yim;
            acc[3] += r1.y * yre - i1.y * yim;
            acc[4] += r2.x * yre - i2.x * yim;
            acc[5] += r2.y * yre - i2.y * yim;
            acc[6] += r3.x * yre - i3.x * yim;
            acc[7] += r3.y * yre - i3.y * yim;
            acc[8] += r4.x * yre - i4.x * yim;
            acc[9] += r4.y * yre - i4.y * yim;
        }
        // fold deconv weights -> fp16 wsig (storage only; math fp32)
        __half* wso = s_wsigh + s * WSIGH_PER_S + j * 24;
#pragma unroll
        for (int k8 = 0; k8 < 2; ++k8) {
            float4 wv0 = make_float4(0.f, 0.f, 0.f, 0.f);
            float4 wv1 = make_float4(0.f, 0.f, 0.f, 0.f);
#pragma unroll
            for (int c = 0; c < 10; ++c) {
                const float a = acc[c];
                float4 w0 = *(const float4*)&s_wt[c * 16 + k8 * 8];
                float4 w1 = *(const float4*)&s_wt[c * 16 + k8 * 8 + 4];
                wv0.x += a * w0.x; wv0.y += a * w0.y;
                wv0.z += a * w0.z; wv0.w += a * w0.w;
                wv1.x += a * w1.x; wv1.y += a * w1.y;
                wv1.z += a * w1.z; wv1.w += a * w1.w;
            }
            __half2 h0 = __floats2half2_rn(wv0.x, wv0.y);
            __half2 h1 = __floats2half2_rn(wv0.z, wv0.w);
            __half2 h2 = __floats2half2_rn(wv1.x, wv1.y);
            __half2 h3 = __floats2half2_rn(wv1.z, wv1.w);
            uint4 v;
            v.x = *reinterpret_cast<unsigned*>(&h0);
            v.y = *reinterpret_cast<unsigned*>(&h1);
            v.z = *reinterpret_cast<unsigned*>(&h2);
            v.w = *reinterpret_cast<unsigned*>(&h3);
            *(uint4*)(wso + k8 * 8) = v;
        }
    }

    const float bias = bt[0];

    // ---- phases 4 & 5: per sample, per 64-output-row strip ----
    for (int s = 0; s < 2; ++s) {
        const __half* wsb = s_wsigh + s * WSIGH_PER_S;
        for (int strip = 0; strip < 2; ++strip) {
            __syncthreads();   // comb free (prev phase5 done / scratch dead)

            // border zeroing
            {
                const int tz = strip ? 33 : 0;   // untouched comb row
                for (int i = tid; i < 8 * 66; i += 512) {
                    const int buf = i / 66, c2 = i - buf * 66;
                    unsigned* dst = (unsigned*)(s_comb + buf * CB_PLANE) +
                                    (tz * CB_ROW >> 1) + c2;
                    *dst = 0u;
                }
                if (s == 0 && strip == 0) {
                    for (int i = tid; i < 8 * 34; i += 512) {
                        const int buf = i / 34, rr2 = i - buf * 34;
                        unsigned* rowp = (unsigned*)(s_comb + buf * CB_PLANE +
                                                     rr2 * CB_ROW);
                        rowp[0] = 0u;
                        rowp[65] = 0u;
                    }
                }
            }

            // phase 4: fill comb planes; packed HFMA2 tap mix (R12 form)
#pragma unroll 2
            for (int p = tid; p < 2112; p += 512) {
                const int rr = p >> 6, x = p & 63;
                const int t = strip ? rr : rr + 1;
                const int iy = strip ? (31 + rr) : rr;
                const int pr = iy * 64 + x;
                const int4 o4 = g_toff[pr];
                const float4 w4 = g_tw[pr];
                const __half2 w0 = __float2half2_rn(w4.x);
                const __half2 w1 = __float2half2_rn(w4.y);
                const __half2 w2 = __float2half2_rn(w4.z);
                const __half2 w3 = __float2half2_rn(w4.w);

                const __half* v0 = wsb + o4.x;
                const __half* v1 = wsb + o4.y;
                const __half* v2 = wsb + o4.z;
                const __half* v3 = wsb + o4.w;
                uint4 a0 = *(const uint4*)(v0);
                uint4 a1 = *(const uint4*)(v0 + 8);
                uint4 b0 = *(const uint4*)(v1);
                uint4 b1 = *(const uint4*)(v1 + 8);
                uint4 c0 = *(const uint4*)(v2);
                uint4 c1 = *(const uint4*)(v2 + 8);
                uint4 d0 = *(const uint4*)(v3);
                uint4 d1 = *(const uint4*)(v3 + 8);

                unsigned acc[8];
                // pairwise tree: (w0*v0 + w1*v1) + (w2*v2 + w3*v3)
                acc[0] = hadd2u(hfma2u(w1, b0.x, hmul2u(w0, a0.x)),
                                hfma2u(w3, d0.x, hmul2u(w2, c0.x)));
                acc[1] = hadd2u(hfma2u(w1, b0.y, hmul2u(w0, a0.y)),
                                hfma2u(w3, d0.y, hmul2u(w2, c0.y)));
                acc[2] = hadd2u(hfma2u(w1, b0.z, hmul2u(w0, a0.z)),
                                hfma2u(w3, d0.z, hmul2u(w2, c0.z)));
                acc[3] = hadd2u(hfma2u(w1, b0.w, hmul2u(w0, a0.w)),
                                hfma2u(w3, d0.w, hmul2u(w2, c0.w)));
                acc[4] = hadd2u(hfma2u(w1, b1.x, hmul2u(w0, a1.x)),
                                hfma2u(w3, d1.x, hmul2u(w2, c1.x)));
                acc[5] = hadd2u(hfma2u(w1, b1.y, hmul2u(w0, a1.y)),
                                hfma2u(w3, d1.y, hmul2u(w2, c1.y)));
                acc[6] = hadd2u(hfma2u(w1, b1.z, hmul2u(w0, a1.z)),
                                hfma2u(w3, d1.z, hmul2u(w2, c1.z)));
                acc[7] = hadd2u(hfma2u(w1, b1.w, hmul2u(w0, a1.w)),
                                hfma2u(w3, d1.w, hmul2u(w2, c1.w)));

                const int baseh = t * CB_ROW + (x + 1) * 2;
#pragma unroll
                for (int kh = 0; kh < 4; ++kh) {
                    *(unsigned*)(s_comb + kh * CB_PLANE + baseh) = acc[2 * kh];
                    *(unsigned*)(s_comb + CB_HI + kh * CB_PLANE + baseh) =
                        acc[2 * kh + 1];
                }
            }
            __syncthreads();

            // phase 5: output = bias + 4 comb halves (wide, conflict-free)
            {
                const int b = tid & 15;          // col block (8 cols)
                const int a = tid >> 4;          // 0..31
                const int blk = a >> 1;          // 4-row block 0..15
                const int halfq = a & 1;
                const int rowbase = 2 * blk;

                const int R1[4] = {1, 2, 2, 3};
                const int KH1[4] = {1, 0, 1, 0};
                const int R2[4] = {0, 1, 1, 2};
                const int KH2[4] = {3, 2, 3, 2};

                float* op = out + (size_t)(2 * n + s) * 16384 +
                            (size_t)(64 * strip) * 128 + 8 * b;

#pragma unroll
                for (int q = 0; q < 2; ++q) {
                    const int dy = 2 * halfq + q;
                    const __half* lo1 = s_comb + KH1[dy] * CB_PLANE +
                                        (rowbase + R1[dy]) * CB_ROW + 8 * b;
                    const __half* lo2 = s_comb + KH2[dy] * CB_PLANE +
                                        (rowbase + R2[dy]) * CB_ROW + 8 * b;
                    const __half* hi1 = lo1 + CB_HI;
                    const __half* hi2 = lo2 + CB_HI;

                    // 24-B window per stream: uint4 (halves 0..7) + uint2 (8..11)
                    uint4 LaA = *(const uint4*)(lo1);
                    uint2 LaB = *(const uint2*)(lo1 + 8);
                    uint4 LbA = *(const uint4*)(lo2);
                    uint2 LbB = *(const uint2*)(lo2 + 8);
                    uint4 HaA = *(const uint4*)(hi1);
                    uint2 HaB = *(const uint2*)(hi1 + 8);
                    uint4 HbA = *(const uint4*)(hi2);
                    uint2 HbB = *(const uint2*)(hi2 + 8);

                    unsigned LL[6], HH[6];
                    LL[1] = hadd2u(LaA.y, LbA.y);
                    LL[2] = hadd2u(LaA.z, LbA.z);
                    LL[3] = hadd2u(LaA.w, LbA.w);
                    LL[4] = hadd2u(LaB.x, LbB.x);
                    LL[5] = hadd2u(LaB.y, LbB.y);
                    HH[0] = hadd2u(HaA.x, HbA.x);
                    HH[1] = hadd2u(HaA.y, HbA.y);
                    HH[2] = hadd2u(HaA.z, HbA.z);
                    HH[3] = hadd2u(HaA.w, HbA.w);
                    HH[4] = hadd2u(HaB.x, HbB.x);

                    float o[8];
#pragma unroll
                    for (int e = 0; e < 8; ++e) {
                        const int il = e + 3;
                        const int ih = e + 1;
                        o[e] = bias + hx(LL[il >> 1], il & 1) +
                               hx(HH[ih >> 1], ih & 1);
                    }
                    float* orow = op + (size_t)(4 * blk + dy) * 128;
                    *(float4*)(orow + 0) = make_float4(o[0], o[1], o[2], o[3]);
                    *(float4*)(orow + 4) = make_float4(o[4], o[5], o[6], o[7]);
                }
            }
        }
    }
}

// ---------------------------------------------------------------------------
extern "C" void kernel_launch(void* const* d_in, const int* in_sizes, int n_in,
                              void* d_out, int out_size) {
    const float* angles   = (const float*)d_in[0];
    const float* spectrum = (const float*)d_in[1];
    const float* wt       = (const float*)d_in[2];
    const float* bt       = (const float*)d_in[3];
    float* out = (float*)d_out;
    (void)in_sizes; (void)n_in; (void)out_size;

    cudaFuncSetAttribute(decoder_kernel,
                         cudaFuncAttributeMaxDynamicSharedMemorySize,
                         SMEM_BYTES);

    prep_kernel<<<54, 256>>>();
    decoder_kernel<<<1024, 512, SMEM_BYTES>>>(angles, spectrum, wt, bt, out);
}